// round 16
// baseline (speedup 1.0000x reference)
#include <cuda_runtime.h>

#define BATCH 512
#define NROWS 256
#define NVECS 8
#define VEC   128
#define DIM   1024
#define EPSF  1e-8f

#define BM 64
#define BR 64
#define PAD (VEC + 4)

#define NDOT    128    // persistent dot CTAs, 2 rounds of 128 tiles each
#define NGROUPS 32     // (b-chunk 64) x (r-chunk 64)
#define NCOMBO  2048   // combo CTAs (512 b * 4 r-chunks)
#define RCHUNK  64

// Scratch: relu'd cosine sims, layout [seg][b][r].
__device__ float g_cos[NVECS * BATCH * NROWS];
// Per-group flags (group = bx*4 + by, bx: b/64, by: r/64). Self-resetting.
__device__ int g_ready[NGROUPS];   // seg tiles completed for this group (target 8)
__device__ int g_done[NGROUPS];    // combo CTAs finished for this group (64 -> reset)

// ---------------------------------------------------------------------------
// Kernel 1 (PDL primary): persistent segmented GEMM. 128 CTAs x 2 rounds.
// Round 0 computes groups 0-15 (released ~halfway), round 1 groups 16-31.
// 256 threads, 4x4 micro-tile, software-pipelined k-loop, fused norms.
// ---------------------------------------------------------------------------
__global__ __launch_bounds__(256) void dot_kernel(const float* __restrict__ query,
                                                  const float* __restrict__ weight) {
    extern __shared__ float smem[];
    float (*qs)[PAD] = (float (*)[PAD])smem;                 // 64 x 132
    float (*ws)[PAD] = (float (*)[PAD])(smem + BM * PAD);    // 64 x 132
    float* qn = smem + (BM + BR) * PAD;                      // 64
    float* wn = qn + BM;                                     // 64

    int cta = blockIdx.x;
    int tid = threadIdx.x;

#if __CUDA_ARCH__ >= 900
    if (tid == 0) cudaTriggerProgrammaticLaunchCompletion();
#endif

    int tx = tid & 15;    // r micro-index
    int ty = tid >> 4;    // b micro-index

#pragma unroll 1
    for (int round = 0; round < 2; round++) {
        int tile = round * NDOT + cta;    // group-major: tile = g*8 + seg
        int g    = tile >> 3;             // 0..31
        int seg  = tile & 7;
        int bbase = (g >> 2) * BM;        // b-chunk
        int rbase = (g & 3) * BR;         // r-chunk

        if (round) __syncthreads();       // protect smem reuse across rounds

        // Tile loads: float4 gmem -> float4 smem.
        for (int i = tid; i < BM * 32; i += 256) {
            int row = i >> 5, c4 = i & 31;
            float4 v = *(const float4*)(query + (size_t)(bbase + row) * DIM + seg * VEC + c4 * 4);
            *(float4*)&qs[row][c4 * 4] = v;
        }
        for (int i = tid; i < BR * 32; i += 256) {
            int row = i >> 5, c4 = i & 31;
            float4 v = *(const float4*)(weight + (size_t)(rbase + row) * DIM + seg * VEC + c4 * 4);
            *(float4*)&ws[row][c4 * 4] = v;
        }
        __syncthreads();

        // Fused inverse norms from smem tiles.
        if (tid < BM) {
            float s = 0.0f;
#pragma unroll 8
            for (int k = 0; k < VEC; k += 4) {
                float4 v = *(const float4*)&qs[tid][k];
                s = fmaf(v.x, v.x, s); s = fmaf(v.y, v.y, s);
                s = fmaf(v.z, v.z, s); s = fmaf(v.w, v.w, s);
            }
            qn[tid] = 1.0f / fmaxf(sqrtf(s), EPSF);
        } else if (tid < BM + BR) {
            int row = tid - BM;
            float s = 0.0f;
#pragma unroll 8
            for (int k = 0; k < VEC; k += 4) {
                float4 v = *(const float4*)&ws[row][k];
                s = fmaf(v.x, v.x, s); s = fmaf(v.y, v.y, s);
                s = fmaf(v.z, v.z, s); s = fmaf(v.w, v.w, s);
            }
            wn[row] = 1.0f / fmaxf(sqrtf(s), EPSF);
        }
        __syncthreads();

        // Software-pipelined 4x4 micro-tile GEMM.
        float acc[4][4] = {};
        float4 qva[4], wva[4], qvb[4], wvb[4];
#pragma unroll
        for (int i = 0; i < 4; i++) qva[i] = *(const float4*)&qs[ty + 16 * i][0];
#pragma unroll
        for (int j = 0; j < 4; j++) wva[j] = *(const float4*)&ws[tx + 16 * j][0];

#define FMA16(QV, WV)                                              \
        _Pragma("unroll")                                          \
        for (int i = 0; i < 4; i++)                                \
            _Pragma("unroll")                                      \
            for (int j = 0; j < 4; j++) {                          \
                acc[i][j] = fmaf(QV[i].x, WV[j].x, acc[i][j]);     \
                acc[i][j] = fmaf(QV[i].y, WV[j].y, acc[i][j]);     \
                acc[i][j] = fmaf(QV[i].z, WV[j].z, acc[i][j]);     \
                acc[i][j] = fmaf(QV[i].w, WV[j].w, acc[i][j]);     \
            }

#pragma unroll
        for (int k = 0; k < VEC; k += 8) {
#pragma unroll
            for (int i = 0; i < 4; i++) qvb[i] = *(const float4*)&qs[ty + 16 * i][k + 4];
#pragma unroll
            for (int j = 0; j < 4; j++) wvb[j] = *(const float4*)&ws[tx + 16 * j][k + 4];
            FMA16(qva, wva)
            if (k + 8 < VEC) {
#pragma unroll
                for (int i = 0; i < 4; i++) qva[i] = *(const float4*)&qs[ty + 16 * i][k + 8];
#pragma unroll
                for (int j = 0; j < 4; j++) wva[j] = *(const float4*)&ws[tx + 16 * j][k + 8];
            }
            FMA16(qvb, wvb)
        }
#undef FMA16

        // Epilogue: scale, relu, coalesced store to [seg][b][r].
        float* dst = g_cos + (size_t)seg * BATCH * NROWS;
#pragma unroll
        for (int i = 0; i < 4; i++) {
            int b = bbase + ty + 16 * i;
            float qi = qn[ty + 16 * i];
#pragma unroll
            for (int j = 0; j < 4; j++) {
                int r = rbase + tx + 16 * j;
                float v = acc[i][j] * qi * wn[tx + 16 * j];
                dst[(size_t)b * NROWS + r] = fmaxf(v, 0.0f);
            }
        }

        // Release this tile: stores -> fence -> barrier -> flag add.
        __threadfence();
        __syncthreads();
        if (tid == 0) atomicAdd(&g_ready[g], 1);
    }
}

// ---------------------------------------------------------------------------
// Kernel 2 (PDL secondary): combo-product expansion. Spins on its group's
// flag, then streams its 64-row chunk. 2 independent rows per iteration ->
// 2 STG.128 in flight per loop body. Plain stores: let L2 absorb the write
// burst; DRAM drain pipelines into the next replay's compute prefix.
// ---------------------------------------------------------------------------
__global__ __launch_bounds__(256, 8) void combo_kernel(float* __restrict__ out) {
    __shared__ float cs[RCHUNK][NVECS];   // 2 KB

    int c   = blockIdx.x;
    int b   = c >> 2;
    int rq  = c & 3;
    int r0  = rq * RCHUNK;
    int grp = (b >> 6) * 4 + rq;          // matches dot group (b/64, r/64)
    int tid = threadIdx.x;

    // Acquire: wait for all 8 seg tiles of this group.
    if (tid == 0) {
        while (atomicAdd(&g_ready[grp], 0) < 8) __nanosleep(128);
    }
    __syncthreads();
    __threadfence();

    // Load this chunk's cos values: 8 contiguous 256B runs (one per seg).
    for (int i = tid; i < RCHUNK * NVECS; i += 256) {
        int seg = i >> 6;
        int rr  = i & 63;
        cs[rr][seg] = g_cos[(size_t)seg * BATCH * NROWS + (size_t)b * NROWS + r0 + rr];
    }
    __syncthreads();

    int sub   = tid & 63;   // combo quad: combos [4*sub, 4*sub+3]
    int rlane = tid >> 6;   // 0..3

    // Per-bit select constants: (bit? 1-v : v) == fmaf(sgn, v, off).
    float sgn[6], off[6];
#pragma unroll
    for (int j = 0; j < 6; j++) {
        int bit = (sub >> j) & 1;
        sgn[j] = bit ? -1.0f : 1.0f;
        off[j] = bit ? 1.0f : 0.0f;
    }

    float* ob = out + (size_t)b * NROWS * 256 + (size_t)r0 * 256;

#pragma unroll
    for (int rg = 0; rg < RCHUNK / 8; rg++) {
        int ra = rg * 8 + rlane;          // row A
        int rb = ra + 4;                  // row B (independent chain)
        float4 aA = *(const float4*)&cs[ra][0];
        float4 aB = *(const float4*)&cs[ra][4];
        float4 bA = *(const float4*)&cs[rb][0];
        float4 bB = *(const float4*)&cs[rb][4];

        // Row A chain
        float a2 = fmaf(sgn[0], aA.z, off[0]);
        float a3 = fmaf(sgn[1], aA.w, off[1]);
        float a4 = fmaf(sgn[2], aB.x, off[2]);
        float a5 = fmaf(sgn[3], aB.y, off[3]);
        float a6 = fmaf(sgn[4], aB.z, off[4]);
        float a7 = fmaf(sgn[5], aB.w, off[5]);
        float pa = ((a2 * a3) * (a4 * a5)) * (a6 * a7);
        // Row B chain
        float b2 = fmaf(sgn[0], bA.z, off[0]);
        float b3 = fmaf(sgn[1], bA.w, off[1]);
        float b4 = fmaf(sgn[2], bB.x, off[2]);
        float b5 = fmaf(sgn[3], bB.y, off[3]);
        float b6 = fmaf(sgn[4], bB.z, off[4]);
        float b7 = fmaf(sgn[5], bB.w, off[5]);
        float pb = ((b2 * b3) * (b4 * b5)) * (b6 * b7);

        float ac0 = aA.x, ac1 = aA.y, an0 = 1.0f - ac0;
        float pa1 = pa * ac1, pan = pa * (1.0f - ac1);
        float4 oA;
        oA.x = pa1 * ac0;  oA.y = pa1 * an0;
        oA.z = pan * ac0;  oA.w = pan * an0;

        float bc0 = bA.x, bc1 = bA.y, bn0 = 1.0f - bc0;
        float pb1 = pb * bc1, pbn = pb * (1.0f - bc1);
        float4 oB;
        oB.x = pb1 * bc0;  oB.y = pb1 * bn0;
        oB.z = pbn * bc0;  oB.w = pbn * bn0;

        ((float4*)(ob + (size_t)ra * 256))[sub] = oA;
        ((float4*)(ob + (size_t)rb * 256))[sub] = oB;
    }

    // Cleanup for the next graph replay: last of this group's 64 combo CTAs
    // zeroes both counters (all readers have passed the spin by then).
    __syncthreads();
    if (tid == 0) {
        int old = atomicAdd(&g_done[grp], 1);
        if (old == 63) {
            g_done[grp]  = 0;
            g_ready[grp] = 0;
            __threadfence();
        }
    }
}

// ---------------------------------------------------------------------------
extern "C" void kernel_launch(void* const* d_in, const int* in_sizes, int n_in,
                              void* d_out, int out_size) {
    const float* query  = (const float*)d_in[0];   // [512, 1024]
    const float* weight = (const float*)d_in[1];   // [256, 1024]
    float* out = (float*)d_out;                    // [512, 256, 256]

    const int dot_smem = ((BM + BR) * PAD + BM + BR) * (int)sizeof(float); // ~68 KB
    (void)cudaFuncSetAttribute(dot_kernel,
                               cudaFuncAttributeMaxDynamicSharedMemorySize,
                               dot_smem);

    // Primary: plain launch (persistent, 2 rounds, progressive releases).
    dot_kernel<<<NDOT, 256, dot_smem>>>(query, weight);

    // Secondary: programmatic dependent launch -> co-runs with dot, gated by
    // per-group flags. Falls back to a plain (serialized) launch on error.
    cudaLaunchConfig_t cfg = {};
    cfg.gridDim  = dim3(NCOMBO);
    cfg.blockDim = dim3(256);
    cfg.dynamicSmemBytes = 0;
    cfg.stream = 0;
    cudaLaunchAttribute attr[1];
    attr[0].id = cudaLaunchAttributeProgrammaticStreamSerialization;
    attr[0].val.programmaticStreamSerializationAllowed = 1;
    cfg.attrs = attr;
    cfg.numAttrs = 1;
    cudaError_t e = cudaLaunchKernelEx(&cfg, combo_kernel, out);
    if (e != cudaSuccess) {
        combo_kernel<<<NCOMBO, 256>>>(out);
    }
}

// round 17
// speedup vs baseline: 1.0676x; 1.0676x over previous
#include <cuda_runtime.h>

#define BATCH 512
#define NROWS 256
#define NVECS 8
#define VEC   128
#define DIM   1024
#define EPSF  1e-8f

#define BM 64
#define BR 64
#define PAD (VEC + 4)

#define NDOT    148    // persistent dot CTAs (one per SM), stride over tiles
#define NTILES  256    // 32 groups x 8 segs, group-major
#define NGROUPS 32     // (b-chunk 64) x (r-chunk 64)
#define NCOMBO  2048   // combo CTAs (512 b * 4 r-chunks)
#define RCHUNK  64

// Scratch: relu'd cosine sims, layout [seg][b][r].
__device__ float g_cos[NVECS * BATCH * NROWS];
// Per-group flags (group = bx*4 + by, bx: b/64, by: r/64). Self-resetting.
__device__ int g_ready[NGROUPS];   // seg tiles completed for this group (target 8)
__device__ int g_done[NGROUPS];    // combo CTAs finished for this group (64 -> reset)

// ---------------------------------------------------------------------------
// Kernel 1 (PDL primary): persistent segmented GEMM. 148 CTAs striding over
// 256 group-major tiles: round 0 (tiles 0..147) completes groups 0..17 at
// ~4.4us; round 1 (108 tiles) overlaps the combo drain. Fused norms.
// ---------------------------------------------------------------------------
__global__ __launch_bounds__(256) void dot_kernel(const float* __restrict__ query,
                                                  const float* __restrict__ weight) {
    extern __shared__ float smem[];
    float (*qs)[PAD] = (float (*)[PAD])smem;                 // 64 x 132
    float (*ws)[PAD] = (float (*)[PAD])(smem + BM * PAD);    // 64 x 132
    float* qn = smem + (BM + BR) * PAD;                      // 64
    float* wn = qn + BM;                                     // 64

    int cta = blockIdx.x;
    int tid = threadIdx.x;

#if __CUDA_ARCH__ >= 900
    if (tid == 0) cudaTriggerProgrammaticLaunchCompletion();
#endif

    int tx = tid & 15;    // r micro-index
    int ty = tid >> 4;    // b micro-index

#pragma unroll 1
    for (int tile = cta; tile < NTILES; tile += NDOT) {
        int g    = tile >> 3;             // 0..31 (group-major release order)
        int seg  = tile & 7;
        int bbase = (g >> 2) * BM;        // b-chunk
        int rbase = (g & 3) * BR;         // r-chunk

        if (tile != cta) __syncthreads(); // protect smem reuse across tiles

        // Tile loads: float4 gmem -> float4 smem.
        for (int i = tid; i < BM * 32; i += 256) {
            int row = i >> 5, c4 = i & 31;
            float4 v = *(const float4*)(query + (size_t)(bbase + row) * DIM + seg * VEC + c4 * 4);
            *(float4*)&qs[row][c4 * 4] = v;
        }
        for (int i = tid; i < BR * 32; i += 256) {
            int row = i >> 5, c4 = i & 31;
            float4 v = *(const float4*)(weight + (size_t)(rbase + row) * DIM + seg * VEC + c4 * 4);
            *(float4*)&ws[row][c4 * 4] = v;
        }
        __syncthreads();

        // Fused inverse norms from smem tiles.
        if (tid < BM) {
            float s = 0.0f;
#pragma unroll 8
            for (int k = 0; k < VEC; k += 4) {
                float4 v = *(const float4*)&qs[tid][k];
                s = fmaf(v.x, v.x, s); s = fmaf(v.y, v.y, s);
                s = fmaf(v.z, v.z, s); s = fmaf(v.w, v.w, s);
            }
            qn[tid] = 1.0f / fmaxf(sqrtf(s), EPSF);
        } else if (tid < BM + BR) {
            int row = tid - BM;
            float s = 0.0f;
#pragma unroll 8
            for (int k = 0; k < VEC; k += 4) {
                float4 v = *(const float4*)&ws[row][k];
                s = fmaf(v.x, v.x, s); s = fmaf(v.y, v.y, s);
                s = fmaf(v.z, v.z, s); s = fmaf(v.w, v.w, s);
            }
            wn[row] = 1.0f / fmaxf(sqrtf(s), EPSF);
        }
        __syncthreads();

        // Software-pipelined 4x4 micro-tile GEMM.
        float acc[4][4] = {};
        float4 qva[4], wva[4], qvb[4], wvb[4];
#pragma unroll
        for (int i = 0; i < 4; i++) qva[i] = *(const float4*)&qs[ty + 16 * i][0];
#pragma unroll
        for (int j = 0; j < 4; j++) wva[j] = *(const float4*)&ws[tx + 16 * j][0];

#define FMA16(QV, WV)                                              \
        _Pragma("unroll")                                          \
        for (int i = 0; i < 4; i++)                                \
            _Pragma("unroll")                                      \
            for (int j = 0; j < 4; j++) {                          \
                acc[i][j] = fmaf(QV[i].x, WV[j].x, acc[i][j]);     \
                acc[i][j] = fmaf(QV[i].y, WV[j].y, acc[i][j]);     \
                acc[i][j] = fmaf(QV[i].z, WV[j].z, acc[i][j]);     \
                acc[i][j] = fmaf(QV[i].w, WV[j].w, acc[i][j]);     \
            }

#pragma unroll
        for (int k = 0; k < VEC; k += 8) {
#pragma unroll
            for (int i = 0; i < 4; i++) qvb[i] = *(const float4*)&qs[ty + 16 * i][k + 4];
#pragma unroll
            for (int j = 0; j < 4; j++) wvb[j] = *(const float4*)&ws[tx + 16 * j][k + 4];
            FMA16(qva, wva)
            if (k + 8 < VEC) {
#pragma unroll
                for (int i = 0; i < 4; i++) qva[i] = *(const float4*)&qs[ty + 16 * i][k + 8];
#pragma unroll
                for (int j = 0; j < 4; j++) wva[j] = *(const float4*)&ws[tx + 16 * j][k + 8];
            }
            FMA16(qvb, wvb)
        }
#undef FMA16

        // Epilogue: scale, relu, coalesced store to [seg][b][r].
        float* dst = g_cos + (size_t)seg * BATCH * NROWS;
#pragma unroll
        for (int i = 0; i < 4; i++) {
            int b = bbase + ty + 16 * i;
            float qi = qn[ty + 16 * i];
#pragma unroll
            for (int j = 0; j < 4; j++) {
                int r = rbase + tx + 16 * j;
                float v = acc[i][j] * qi * wn[tx + 16 * j];
                dst[(size_t)b * NROWS + r] = fmaxf(v, 0.0f);
            }
        }

        // Release this tile: stores -> fence -> barrier -> flag add.
        __threadfence();
        __syncthreads();
        if (tid == 0) atomicAdd(&g_ready[g], 1);
    }
}

// ---------------------------------------------------------------------------
// Kernel 2 (PDL secondary): combo-product expansion (R15-proven config).
// Spins on its group's flag, then streams its 64-row chunk with .cs stores.
// ---------------------------------------------------------------------------
__global__ __launch_bounds__(256, 8) void combo_kernel(float* __restrict__ out) {
    __shared__ float cs[RCHUNK][NVECS];   // 2 KB

    int c   = blockIdx.x;
    int b   = c >> 2;
    int rq  = c & 3;
    int r0  = rq * RCHUNK;
    int grp = (b >> 6) * 4 + rq;          // matches dot group (b/64, r/64)
    int tid = threadIdx.x;

    // Acquire: wait for all 8 seg tiles of this group.
    if (tid == 0) {
        while (atomicAdd(&g_ready[grp], 0) < 8) __nanosleep(64);
    }
    __syncthreads();
    __threadfence();

    // Load this chunk's cos values: 8 contiguous 256B runs (one per seg).
    for (int i = tid; i < RCHUNK * NVECS; i += 256) {
        int seg = i >> 6;
        int rr  = i & 63;
        cs[rr][seg] = g_cos[(size_t)seg * BATCH * NROWS + (size_t)b * NROWS + r0 + rr];
    }
    __syncthreads();

    int sub   = tid & 63;   // combo quad: combos [4*sub, 4*sub+3]
    int rlane = tid >> 6;   // 0..3

    // Per-bit select constants: (bit? 1-v : v) == fmaf(sgn, v, off).
    float sgn[6], off[6];
#pragma unroll
    for (int j = 0; j < 6; j++) {
        int bit = (sub >> j) & 1;
        sgn[j] = bit ? -1.0f : 1.0f;
        off[j] = bit ? 1.0f : 0.0f;
    }

    float* ob = out + (size_t)b * NROWS * 256 + (size_t)r0 * 256;

#pragma unroll
    for (int rg = 0; rg < RCHUNK / 4; rg++) {
        int r = rg * 4 + rlane;
        float4 cA = *(const float4*)&cs[r][0];   // c0..c3
        float4 cB = *(const float4*)&cs[r][4];   // c4..c7

        float t2 = fmaf(sgn[0], cA.z, off[0]);
        float t3 = fmaf(sgn[1], cA.w, off[1]);
        float t4 = fmaf(sgn[2], cB.x, off[2]);
        float t5 = fmaf(sgn[3], cB.y, off[3]);
        float t6 = fmaf(sgn[4], cB.z, off[4]);
        float t7 = fmaf(sgn[5], cB.w, off[5]);
        float p  = ((t2 * t3) * (t4 * t5)) * (t6 * t7);

        float c0 = cA.x, c1 = cA.y;
        float n0 = 1.0f - c0;
        float pc1 = p * c1;
        float pn1 = p * (1.0f - c1);
        float4 o;
        o.x = pc1 * c0;    // combo bits (0,0)
        o.y = pc1 * n0;    // (1,0)
        o.z = pn1 * c0;    // (0,1)
        o.w = pn1 * n0;    // (1,1)

        __stcs((float4*)(ob + (size_t)r * 256) + sub, o);
    }

    // Cleanup for the next graph replay: last of this group's 64 combo CTAs
    // zeroes both counters (all readers have passed the spin by then).
    __syncthreads();
    if (tid == 0) {
        int old = atomicAdd(&g_done[grp], 1);
        if (old == 63) {
            g_done[grp]  = 0;
            g_ready[grp] = 0;
            __threadfence();
        }
    }
}

// ---------------------------------------------------------------------------
extern "C" void kernel_launch(void* const* d_in, const int* in_sizes, int n_in,
                              void* d_out, int out_size) {
    const float* query  = (const float*)d_in[0];   // [512, 1024]
    const float* weight = (const float*)d_in[1];   // [256, 1024]
    float* out = (float*)d_out;                    // [512, 256, 256]

    const int dot_smem = ((BM + BR) * PAD + BM + BR) * (int)sizeof(float); // ~68 KB
    (void)cudaFuncSetAttribute(dot_kernel,
                               cudaFuncAttributeMaxDynamicSharedMemorySize,
                               dot_smem);

    // Primary: plain launch (persistent, tile-striding, progressive releases).
    dot_kernel<<<NDOT, 256, dot_smem>>>(query, weight);

    // Secondary: programmatic dependent launch -> co-runs with dot, gated by
    // per-group flags. Falls back to a plain (serialized) launch on error.
    cudaLaunchConfig_t cfg = {};
    cfg.gridDim  = dim3(NCOMBO);
    cfg.blockDim = dim3(256);
    cfg.dynamicSmemBytes = 0;
    cfg.stream = 0;
    cudaLaunchAttribute attr[1];
    attr[0].id = cudaLaunchAttributeProgrammaticStreamSerialization;
    attr[0].val.programmaticStreamSerializationAllowed = 1;
    cfg.attrs = attr;
    cfg.numAttrs = 1;
    cudaError_t e = cudaLaunchKernelEx(&cfg, combo_kernel, out);
    if (e != cudaSuccess) {
        combo_kernel<<<NCOMBO, 256>>>(out);
    }
}